// round 3
// baseline (speedup 1.0000x reference)
#include <cuda_runtime.h>

#define BB   512
#define SS   17
#define LL   81
#define VV   13030
#define ENCD 240
#define OED  80
#define PED  60
#define IND  380     // ENC + OE + PE
#define HD   200
#define G4H  800     // 4*H
#define KIN  580     // IND + HD

// ---------------- scratch (static device globals; no allocation) ----------------
__device__ float g_loc_enc[SS * BB * ENCD];     // [t][b][d]
__device__ float g_power_emb[BB * PED];
__device__ int   g_invalid[BB];
__device__ float g_h[BB * HD];
__device__ float g_c[BB * HD];
__device__ float g_oe[BB * OED];
__device__ float g_gates[BB * G4H];
__device__ unsigned long long g_amax[BB];
__device__ unsigned g_keys[2 * SS];             // (k1,k2) per step

// ---------------- threefry2x32 (matches jax/_src/prng.py reference) ----------------
__device__ __forceinline__ uint2 tf2x32(unsigned k0, unsigned k1,
                                        unsigned x0, unsigned x1) {
    unsigned ks2 = k0 ^ k1 ^ 0x1BD11BDAu;
    x0 += k0; x1 += k1;
#define TFR(r) { x0 += x1; x1 = __funnelshift_l(x1, x1, (r)); x1 ^= x0; }
    TFR(13) TFR(15) TFR(26) TFR(6)
    x0 += k1; x1 += ks2 + 1u;
    TFR(17) TFR(29) TFR(16) TFR(24)
    x0 += ks2; x1 += k0 + 2u;
    TFR(13) TFR(15) TFR(26) TFR(6)
    x0 += k0; x1 += k1 + 3u;
    TFR(17) TFR(29) TFR(16) TFR(24)
    x0 += k1; x1 += ks2 + 4u;
    TFR(13) TFR(15) TFR(26) TFR(6)
    x0 += ks2; x1 += k0 + 5u;
#undef TFR
    return make_uint2(x0, x1);
}

// ---------------- accurate fp32 natural log (fdlibm e_logf; fast-math-proof) ----------------
__device__ __forceinline__ float alogf(float x) {
    // assumes x > 0 and normal (uniform >= FLT_MIN guarantees this)
    int ib = __float_as_int(x);
    int k  = ((ib >> 23) & 0xFF) - 126;
    float m = __int_as_float((ib & 0x007FFFFF) | 0x3F000000);  // [0.5,1)
    if (m < 0.70710678f) { m = m + m; k -= 1; }
    float f = m - 1.0f;
    float s = f / (2.0f + f);
    float z = s * s;
    float w = z * z;
    float t1 = w * (0.40000972152f + w * 0.24279078841f);
    float t2 = z * (0.66666662693f + w * 0.28498786688f);
    float R  = t2 + t1;
    float hfsq = 0.5f * f * f;
    float dk = (float)k;
    return dk * 0.69313812256f - ((hfsq - (s * (hfsq + R) + dk * 9.0580006145e-06f)) - f);
}

// ---------------- kernel A: precompute loc_enc / power_emb / invalid / keys / zero-state ----------------
__global__ __launch_bounds__(256) void precompute_kernel(
    const float* __restrict__ enc, const int* __restrict__ loc_idxs,
    const float* __restrict__ power_1h, const float* __restrict__ power_W,
    const float* __restrict__ power_b, const float* __restrict__ master) {
    __shared__ float sM[LL * LL];
    __shared__ float sAl[SS][LL];
    __shared__ float sDen[SS];
    __shared__ int   sLoc[LL];
    int b = blockIdx.x;
    int tid = threadIdx.x;

    for (int i = tid; i < LL * LL; i += 256) sM[i] = master[i];
    if (tid < LL) sLoc[tid] = loc_idxs[b * LL + tid];
    for (int i = tid; i < HD; i += 256) { g_h[b * HD + i] = 0.f; g_c[b * HD + i] = 0.f; }
    for (int i = tid; i < OED; i += 256) g_oe[b * OED + i] = 0.f;
    if (tid == 0) g_amax[b] = 0ULL;
    if (tid < PED) {
        float acc = power_b[tid];
        for (int j = 0; j < 7; ++j) acc += power_1h[b * 7 + j] * power_W[tid * 7 + j];
        g_power_emb[b * PED + tid] = acc;
    }
    if (b == 0 && tid < SS) {  // keys[t] = threefry2x32((0,42),(0,t)) -> both words
        uint2 r = tf2x32(0u, 42u, 0u, (unsigned)tid);
        g_keys[2 * tid]     = r.x;
        g_keys[2 * tid + 1] = r.y;
    }
    __syncthreads();

    if (tid == 0) {
        int any = 0;
        for (int l = 0; l < LL; ++l) any |= (sLoc[l] != -1);
        g_invalid[b] = !any;
    }
    // align_all[t][j] = sum_l sel(t,l) * M[l][j]
    for (int e = tid; e < SS * LL; e += 256) {
        int t = e / LL, j = e % LL;
        float a = 0.f;
        for (int l = 0; l < LL; ++l) {
            int li = sLoc[l];
            if (li == t || li == -2) a += sM[l * LL + j];
        }
        sAl[t][j] = a;
    }
    __syncthreads();
    if (tid < SS) {
        float d = 0.f;
        for (int j = 0; j < LL; ++j) d += sAl[tid][j];
        sDen[tid] = d;
    }
    __syncthreads();
    for (int e = tid; e < SS * LL; e += 256) {
        int t = e / LL, j = e % LL;
        float d = sDen[t];
        sAl[t][j] = (d != 0.f) ? sAl[t][j] / d : 0.f;
    }
    __syncthreads();
    // loc_enc: enc[b] read once, 17 accumulators per thread
    if (tid < ENCD) {
        float acc[SS];
#pragma unroll
        for (int t = 0; t < SS; ++t) acc[t] = 0.f;
        for (int l = 0; l < LL; ++l) {
            float v = enc[((size_t)b * LL + l) * ENCD + tid];
#pragma unroll
            for (int t = 0; t < SS; ++t) acc[t] += sAl[t][l] * v;
        }
#pragma unroll
        for (int t = 0; t < SS; ++t)
            g_loc_enc[((size_t)t * BB + b) * ENCD + tid] = acc[t];
    }
}

// ---------------- G1: gates GEMM  C[512,800] = X[512,580] @ W^T + biases ----------------
__global__ __launch_bounds__(256) void gates_gemm_kernel(
    const float* __restrict__ W_ih, const float* __restrict__ W_hh,
    const float* __restrict__ b_ih, const float* __restrict__ b_hh, int t) {
    __shared__ float As[16][65];
    __shared__ float Bs[16][65];
    int tid = threadIdx.x;
    int tx = tid & 15, ty = tid >> 4;
    int n0 = blockIdx.x * 64, m0 = blockIdx.y * 64;
    const float* locenc = g_loc_enc + (size_t)t * BB * ENCD;
    float acc[4][4] = {};
    int lm = tid >> 2;          // 0..63
    int lk = (tid & 3) * 4;     // 0,4,8,12

    for (int k0 = 0; k0 < KIN; k0 += 16) {
        int bidx = m0 + lm;
#pragma unroll
        for (int i = 0; i < 4; ++i) {
            int k = k0 + lk + i;
            float v = 0.f;
            if (k < KIN) {
                if (k < ENCD)            v = locenc[bidx * ENCD + k];
                else if (k < ENCD + OED) v = g_oe[bidx * OED + (k - ENCD)];
                else if (k < IND)        v = g_power_emb[bidx * PED + (k - ENCD - OED)];
                else                     v = g_h[bidx * HD + (k - IND)];
            }
            As[lk + i][lm] = v;
        }
        int jj = n0 + lm;
#pragma unroll
        for (int i = 0; i < 4; ++i) {
            int k = k0 + lk + i;
            float v = 0.f;
            if (k < KIN && jj < G4H)
                v = (k < IND) ? W_ih[jj * IND + k] : W_hh[jj * HD + (k - IND)];
            Bs[lk + i][lm] = v;
        }
        __syncthreads();
#pragma unroll
        for (int c = 0; c < 16; ++c) {
            float a[4], bv[4];
#pragma unroll
            for (int i = 0; i < 4; ++i) a[i] = As[c][ty * 4 + i];
#pragma unroll
            for (int j = 0; j < 4; ++j) bv[j] = Bs[c][tx * 4 + j];
#pragma unroll
            for (int i = 0; i < 4; ++i)
#pragma unroll
                for (int j = 0; j < 4; ++j) acc[i][j] = fmaf(a[i], bv[j], acc[i][j]);
        }
        __syncthreads();
    }
#pragma unroll
    for (int i = 0; i < 4; ++i) {
        int b = m0 + ty * 4 + i;
#pragma unroll
        for (int j = 0; j < 4; ++j) {
            int u = n0 + tx * 4 + j;
            if (u < G4H) g_gates[b * G4H + u] = acc[i][j] + b_ih[u] + b_hh[u];
        }
    }
}

// ---------------- G2: LSTM pointwise update ----------------
__global__ void lstm_update_kernel() {
    int idx = blockIdx.x * blockDim.x + threadIdx.x;
    if (idx >= BB * HD) return;
    int b = idx / HD, u = idx - b * HD;
    const float* g = g_gates + b * G4H;
    float gi = g[u], gf = g[u + HD], gg = g[u + 2 * HD], go = g[u + 3 * HD];
    float si = 1.f / (1.f + expf(-gi));
    float sf = 1.f / (1.f + expf(-gf));
    float so = 1.f / (1.f + expf(-go));
    float c = sf * g_c[idx] + si * tanhf(gg);
    float h = so * tanhf(c);
    g_c[idx] = c;
    g_h[idx] = h;
}

// ---------------- G3: scores GEMM + mask + gumbel + partial argmax ----------------
__global__ __launch_bounds__(256) void scores_kernel(
    const float* __restrict__ out_W, const float* __restrict__ out_b,
    const unsigned* __restrict__ order_masks, float* __restrict__ scores_out, int t) {
    __shared__ float As[16][65];
    __shared__ float Bs[16][65];
    __shared__ unsigned long long sbest[64];
    int tid = threadIdx.x;
    int tx = tid & 15, ty = tid >> 4;
    int v0 = blockIdx.x * 64, m0 = blockIdx.y * 64;
    if (tid < 64) sbest[tid] = 0ULL;
    float acc[4][4] = {};
    int lm = tid >> 2;
    int lk = (tid & 3) * 4;

    for (int k0 = 0; k0 < HD; k0 += 16) {
#pragma unroll
        for (int i = 0; i < 4; ++i) {
            int k = k0 + lk + i;
            As[lk + i][lm] = (k < HD) ? g_h[(m0 + lm) * HD + k] : 0.f;
        }
        int vv = v0 + lm;
#pragma unroll
        for (int i = 0; i < 4; ++i) {
            int k = k0 + lk + i;
            Bs[lk + i][lm] = (k < HD && vv < VV) ? out_W[(size_t)vv * HD + k] : 0.f;
        }
        __syncthreads();
#pragma unroll
        for (int c = 0; c < 16; ++c) {
            float a[4], bv[4];
#pragma unroll
            for (int i = 0; i < 4; ++i) a[i] = As[c][ty * 4 + i];
#pragma unroll
            for (int j = 0; j < 4; ++j) bv[j] = Bs[c][tx * 4 + j];
#pragma unroll
            for (int i = 0; i < 4; ++i)
#pragma unroll
                for (int j = 0; j < 4; ++j) acc[i][j] = fmaf(a[i], bv[j], acc[i][j]);
        }
        __syncthreads();
    }

    unsigned k1t = g_keys[2 * t], k2t = g_keys[2 * t + 1];
#pragma unroll
    for (int i = 0; i < 4; ++i) {
        int b = m0 + ty * 4 + i;
        int inv = g_invalid[b];
        unsigned long long best = 0ULL;
#pragma unroll
        for (int j = 0; j < 4; ++j) {
            int v = v0 + tx * 4 + j;
            if (v >= VV) continue;
            float s = acc[i][j] + out_b[v];
            size_t mi = ((size_t)b * SS + t) * (size_t)VV + v;
            bool m = inv || (order_masks[mi] != 0u);
            float sm = fminf(s, m ? 9.0e8f : -1.0e8f);
            if (scores_out) scores_out[mi] = sm;
            if (m) {
                // partitionable threefry: bits(n) = y0 ^ y1 of hash(key_t, (0, n))
                unsigned n = (unsigned)(b * VV + v);
                uint2 r = tf2x32(k1t, k2t, 0u, n);
                unsigned bits = r.x ^ r.y;
                float uf = __uint_as_float((bits >> 9) | 0x3F800000u) - 1.0f;
                uf = fmaxf(uf + 1.17549435e-38f, 1.17549435e-38f);
                float gum = -alogf(-alogf(uf));
                float cand = sm + gum;
                unsigned ub = __float_as_uint(cand);
                ub = (ub & 0x80000000u) ? ~ub : (ub | 0x80000000u);
                unsigned long long packed =
                    ((unsigned long long)ub << 32) | (unsigned)(~(unsigned)v);
                if (packed > best) best = packed;
            }
        }
        if (best) atomicMax(&sbest[ty * 4 + i], best);
    }
    __syncthreads();
    if (tid < 64 && sbest[tid]) atomicMax(&g_amax[m0 + tid], sbest[tid]);
}

// ---------------- G4: finalize sample -> idx output + order embedding, reset slot ----------------
__global__ void sample_finish_kernel(const float* __restrict__ order_embedding,
                                     float* __restrict__ idx_out, int t) {
    int b = blockIdx.x;
    __shared__ int sidx;
    if (threadIdx.x == 0) {
        unsigned long long p = g_amax[b];
        int idx = (p == 0ULL) ? 0 : (int)(~(unsigned)(p & 0xFFFFFFFFu));
        if (idx < 0) idx = 0;
        if (idx >= VV) idx = VV - 1;
        sidx = idx;
        g_amax[b] = 0ULL;
        if (idx_out) idx_out[b * SS + t] = (float)idx;
    }
    __syncthreads();
    int idx = sidx;
    if (threadIdx.x < OED)
        g_oe[b * OED + threadIdx.x] = order_embedding[(size_t)idx * OED + threadIdx.x];
}

// ---------------- launch ----------------
extern "C" void kernel_launch(void* const* d_in, const int* in_sizes, int n_in,
                              void* d_out, int out_size) {
    const float*    enc        = (const float*)d_in[0];
    // d_in[1] = in_adj_phase (unused by the reference)
    const int*      loc_idxs   = (const int*)d_in[2];
    const unsigned* ord_masks  = (const unsigned*)d_in[3];
    const float*    power_1h   = (const float*)d_in[4];
    const float*    order_emb  = (const float*)d_in[5];
    const float*    power_W    = (const float*)d_in[6];
    const float*    power_b    = (const float*)d_in[7];
    const float*    W_ih       = (const float*)d_in[8];
    const float*    W_hh       = (const float*)d_in[9];
    const float*    b_ih       = (const float*)d_in[10];
    const float*    b_hh       = (const float*)d_in[11];
    const float*    out_W      = (const float*)d_in[12];
    const float*    out_b      = (const float*)d_in[13];
    const float*    master     = (const float*)d_in[14];

    float* out = (float*)d_out;
    float* idx_out = nullptr;
    float* scores_out = nullptr;
    const long long NSC = (long long)BB * SS * VV;
    if ((long long)out_size == NSC + (long long)BB * SS) { idx_out = out; scores_out = out + BB * SS; }
    else if ((long long)out_size == NSC)                 { scores_out = out; }
    else if (out_size == BB * SS)                        { idx_out = out; }
    else { scores_out = out; }  // best effort

    precompute_kernel<<<BB, 256>>>(enc, loc_idxs, power_1h, power_W, power_b, master);

    dim3 g1grid((G4H + 63) / 64, BB / 64);
    dim3 g3grid((VV + 63) / 64, BB / 64);
    for (int t = 0; t < SS; ++t) {
        gates_gemm_kernel<<<g1grid, 256>>>(W_ih, W_hh, b_ih, b_hh, t);
        lstm_update_kernel<<<(BB * HD + 255) / 256, 256>>>();
        scores_kernel<<<g3grid, 256>>>(out_W, out_b, ord_masks, scores_out, t);
        sample_finish_kernel<<<BB, 128>>>(order_emb, idx_out, t);
    }
}

// round 6
// speedup vs baseline: 1.1375x; 1.1375x over previous
#include <cuda_runtime.h>

#define BB   512
#define SS   17
#define LL   81
#define VV   13030
#define ENCD 240
#define OED  80
#define PED  60
#define IND  380     // ENC + OE + PE
#define HD   200
#define G4H  800     // 4*H
#define KIN  580     // IND + HD

// ---------------- scratch (static device globals; no allocation) ----------------
__device__ __align__(16) float g_loc_enc[SS * BB * ENCD];     // [t][b][d]
__device__ __align__(16) float g_power_emb[BB * PED];
__device__ int   g_invalid[BB];
__device__ __align__(16) float g_h[BB * HD];
__device__ __align__(16) float g_c[BB * HD];
__device__ __align__(16) float g_oe[BB * OED];
__device__ __align__(16) float g_gates[BB * G4H];
__device__ unsigned long long g_amax[BB];
__device__ unsigned g_keys[2 * SS];             // (k1,k2) per step

// ---------------- threefry2x32 (matches jax/_src/prng.py reference) ----------------
__device__ __forceinline__ uint2 tf2x32(unsigned k0, unsigned k1,
                                        unsigned x0, unsigned x1) {
    unsigned ks2 = k0 ^ k1 ^ 0x1BD11BDAu;
    x0 += k0; x1 += k1;
#define TFR(r) { x0 += x1; x1 = __funnelshift_l(x1, x1, (r)); x1 ^= x0; }
    TFR(13) TFR(15) TFR(26) TFR(6)
    x0 += k1; x1 += ks2 + 1u;
    TFR(17) TFR(29) TFR(16) TFR(24)
    x0 += ks2; x1 += k0 + 2u;
    TFR(13) TFR(15) TFR(26) TFR(6)
    x0 += k0; x1 += k1 + 3u;
    TFR(17) TFR(29) TFR(16) TFR(24)
    x0 += k1; x1 += ks2 + 4u;
    TFR(13) TFR(15) TFR(26) TFR(6)
    x0 += ks2; x1 += k0 + 5u;
#undef TFR
    return make_uint2(x0, x1);
}

// ---------------- accurate fp32 natural log (fdlibm e_logf; fast-math-proof) ----------------
__device__ __forceinline__ float alogf(float x) {
    int ib = __float_as_int(x);
    int k  = ((ib >> 23) & 0xFF) - 126;
    float m = __int_as_float((ib & 0x007FFFFF) | 0x3F000000);  // [0.5,1)
    if (m < 0.70710678f) { m = m + m; k -= 1; }
    float f = m - 1.0f;
    float s = f / (2.0f + f);
    float z = s * s;
    float w = z * z;
    float t1 = w * (0.40000972152f + w * 0.24279078841f);
    float t2 = z * (0.66666662693f + w * 0.28498786688f);
    float R  = t2 + t1;
    float hfsq = 0.5f * f * f;
    float dk = (float)k;
    return dk * 0.69313812256f - ((hfsq - (s * (hfsq + R) + dk * 9.0580006145e-06f)) - f);
}

// ---------------- tf32 helpers ----------------
__device__ __forceinline__ unsigned f2tf32(float x) {
    unsigned r;
    asm("cvt.rna.tf32.f32 %0, %1;" : "=r"(r) : "f"(x));
    return r;
}
__device__ __forceinline__ void mma_tf32(float* c, const unsigned* a, const unsigned* b) {
    asm volatile(
        "mma.sync.aligned.m16n8k8.row.col.f32.tf32.tf32.f32 "
        "{%0,%1,%2,%3}, {%4,%5,%6,%7}, {%8,%9}, {%0,%1,%2,%3};\n"
        : "+f"(c[0]), "+f"(c[1]), "+f"(c[2]), "+f"(c[3])
        : "r"(a[0]), "r"(a[1]), "r"(a[2]), "r"(a[3]), "r"(b[0]), "r"(b[1]));
}
// split fp32 -> (hi, lo) tf32 pair: x ~= hi + lo, residual <= 2^-22 |x|
__device__ __forceinline__ void split1(float x, unsigned& hi, unsigned& lo) {
    hi = f2tf32(x);
    lo = f2tf32(x - __uint_as_float(hi));
}
__device__ __forceinline__ void split4(float4 v, uint4& hi, uint4& lo) {
    split1(v.x, hi.x, lo.x);
    split1(v.y, hi.y, lo.y);
    split1(v.z, hi.z, lo.z);
    split1(v.w, hi.w, lo.w);
}

// ---------------- kernel A: precompute (unchanged, known-correct) ----------------
__global__ __launch_bounds__(256) void precompute_kernel(
    const float* __restrict__ enc, const int* __restrict__ loc_idxs,
    const float* __restrict__ power_1h, const float* __restrict__ power_W,
    const float* __restrict__ power_b, const float* __restrict__ master) {
    __shared__ float sM[LL * LL];
    __shared__ float sAl[SS][LL];
    __shared__ float sDen[SS];
    __shared__ int   sLoc[LL];
    int b = blockIdx.x;
    int tid = threadIdx.x;

    for (int i = tid; i < LL * LL; i += 256) sM[i] = master[i];
    if (tid < LL) sLoc[tid] = loc_idxs[b * LL + tid];
    for (int i = tid; i < HD; i += 256) { g_h[b * HD + i] = 0.f; g_c[b * HD + i] = 0.f; }
    for (int i = tid; i < OED; i += 256) g_oe[b * OED + i] = 0.f;
    if (tid == 0) g_amax[b] = 0ULL;
    if (tid < PED) {
        float acc = power_b[tid];
        for (int j = 0; j < 7; ++j) acc += power_1h[b * 7 + j] * power_W[tid * 7 + j];
        g_power_emb[b * PED + tid] = acc;
    }
    if (b == 0 && tid < SS) {
        uint2 r = tf2x32(0u, 42u, 0u, (unsigned)tid);
        g_keys[2 * tid]     = r.x;
        g_keys[2 * tid + 1] = r.y;
    }
    __syncthreads();

    if (tid == 0) {
        int any = 0;
        for (int l = 0; l < LL; ++l) any |= (sLoc[l] != -1);
        g_invalid[b] = !any;
    }
    for (int e = tid; e < SS * LL; e += 256) {
        int t = e / LL, j = e % LL;
        float a = 0.f;
        for (int l = 0; l < LL; ++l) {
            int li = sLoc[l];
            if (li == t || li == -2) a += sM[l * LL + j];
        }
        sAl[t][j] = a;
    }
    __syncthreads();
    if (tid < SS) {
        float d = 0.f;
        for (int j = 0; j < LL; ++j) d += sAl[tid][j];
        sDen[tid] = d;
    }
    __syncthreads();
    for (int e = tid; e < SS * LL; e += 256) {
        int t = e / LL, j = e % LL;
        float d = sDen[t];
        sAl[t][j] = (d != 0.f) ? sAl[t][j] / d : 0.f;
    }
    __syncthreads();
    if (tid < ENCD) {
        float acc[SS];
#pragma unroll
        for (int t = 0; t < SS; ++t) acc[t] = 0.f;
        for (int l = 0; l < LL; ++l) {
            float v = enc[((size_t)b * LL + l) * ENCD + tid];
#pragma unroll
        for (int t = 0; t < SS; ++t) acc[t] += sAl[t][l] * v;
        }
#pragma unroll
        for (int t = 0; t < SS; ++t)
            g_loc_enc[((size_t)t * BB + b) * ENCD + tid] = acc[t];
    }
}

// ---------------- G1: gates tf32x3-MMA GEMM  g_gates[b][u] = x @ Wcat^T + biases ----------------
// K reordered to [h(200) | enc(240) | oe(80) | pe(60)]; all boundaries float4-aligned.
__global__ __launch_bounds__(256) void gates_mma_kernel(
    const float* __restrict__ W_ih, const float* __restrict__ W_hh,
    const float* __restrict__ b_ih, const float* __restrict__ b_hh, int t) {
    __shared__ __align__(16) unsigned AsH[128][20];
    __shared__ __align__(16) unsigned AsL[128][20];
    __shared__ __align__(16) unsigned BsH[64][20];
    __shared__ __align__(16) unsigned BsL[64][20];
    __shared__ float sBias[128];
    int tid = threadIdx.x;
    int u0 = blockIdx.x * 128, b0 = blockIdx.y * 64;
    int lane = tid & 31, warp = tid >> 5;
    int wv = warp & 1, wb = warp >> 1;     // warp grid 2 (u) x 4 (b)
    int g = lane >> 2, tig = lane & 3;
    const float* locenc = g_loc_enc + (size_t)t * BB * ENCD;

    if (tid < 128) {
        int u = u0 + tid;
        sBias[tid] = (u < G4H) ? (b_ih[u] + b_hh[u]) : 0.f;
    }

    float acc[4][2][4];
#pragma unroll
    for (int mt = 0; mt < 4; ++mt)
#pragma unroll
        for (int nt = 0; nt < 2; ++nt)
#pragma unroll
            for (int q = 0; q < 4; ++q) acc[mt][nt][q] = 0.f;

    int arow = tid >> 1, akp = (tid & 1) * 8;    // A: 8 floats/thread
    int brow = tid >> 2, bkp = (tid & 3) * 4;    // B: 4 floats/thread

    for (int k0 = 0; k0 < 592; k0 += 16) {
        // ---- A: weight row (u), reordered k ----
        int u = u0 + arow;
#pragma unroll
        for (int half = 0; half < 2; ++half) {
            int k = k0 + akp + half * 4;
            float4 a = make_float4(0.f, 0.f, 0.f, 0.f);
            if (u < G4H) {
                if (k < HD)       a = *(const float4*)(W_hh + (size_t)u * HD + k);
                else if (k < KIN) a = *(const float4*)(W_ih + (size_t)u * IND + (k - HD));
            }
            uint4 hi, lo; split4(a, hi, lo);
            *(uint4*)&AsH[arow][akp + half * 4] = hi;
            *(uint4*)&AsL[arow][akp + half * 4] = lo;
        }
        // ---- B: x row (b), reordered k ----
        {
            int bb = b0 + brow;
            int k = k0 + bkp;
            float4 x = make_float4(0.f, 0.f, 0.f, 0.f);
            if (k < HD)                   x = *(const float4*)(g_h + bb * HD + k);
            else if (k < HD + ENCD)       x = *(const float4*)(locenc + bb * ENCD + (k - HD));
            else if (k < HD + ENCD + OED) x = *(const float4*)(g_oe + bb * OED + (k - HD - ENCD));
            else if (k < KIN)             x = *(const float4*)(g_power_emb + bb * PED + (k - HD - ENCD - OED));
            uint4 hi, lo; split4(x, hi, lo);
            *(uint4*)&BsH[brow][bkp] = hi;
            *(uint4*)&BsL[brow][bkp] = lo;
        }
        __syncthreads();
#pragma unroll
        for (int kk = 0; kk < 16; kk += 8) {
            unsigned afh[4][4], afl[4][4], bfh[2][2], bfl[2][2];
#pragma unroll
            for (int mt = 0; mt < 4; ++mt) {
                int r = wv * 64 + mt * 16 + g;
                afh[mt][0] = AsH[r][kk + tig];
                afh[mt][1] = AsH[r + 8][kk + tig];
                afh[mt][2] = AsH[r][kk + tig + 4];
                afh[mt][3] = AsH[r + 8][kk + tig + 4];
                afl[mt][0] = AsL[r][kk + tig];
                afl[mt][1] = AsL[r + 8][kk + tig];
                afl[mt][2] = AsL[r][kk + tig + 4];
                afl[mt][3] = AsL[r + 8][kk + tig + 4];
            }
#pragma unroll
            for (int nt = 0; nt < 2; ++nt) {
                int c = wb * 16 + nt * 8 + g;
                bfh[nt][0] = BsH[c][kk + tig];
                bfh[nt][1] = BsH[c][kk + tig + 4];
                bfl[nt][0] = BsL[c][kk + tig];
                bfl[nt][1] = BsL[c][kk + tig + 4];
            }
#pragma unroll
            for (int mt = 0; mt < 4; ++mt)
#pragma unroll
                for (int nt = 0; nt < 2; ++nt) {
                    mma_tf32(acc[mt][nt], afh[mt], bfl[nt]);
                    mma_tf32(acc[mt][nt], afl[mt], bfh[nt]);
                    mma_tf32(acc[mt][nt], afh[mt], bfh[nt]);
                }
        }
        __syncthreads();
    }
    // epilogue: write gates (layout unchanged: [b][u])
#pragma unroll
    for (int nt = 0; nt < 2; ++nt)
#pragma unroll
        for (int cc = 0; cc < 2; ++cc) {
            int b = b0 + wb * 16 + nt * 8 + 2 * tig + cc;
#pragma unroll
            for (int mt = 0; mt < 4; ++mt)
#pragma unroll
                for (int rr = 0; rr < 2; ++rr) {
                    int u = u0 + wv * 64 + mt * 16 + g + rr * 8;
                    if (u < G4H)
                        g_gates[b * G4H + u] = acc[mt][nt][rr * 2 + cc] + sBias[u - u0];
                }
        }
}

// ---------------- G2: LSTM pointwise update ----------------
__global__ void lstm_update_kernel() {
    int idx = blockIdx.x * blockDim.x + threadIdx.x;
    if (idx >= BB * HD) return;
    int b = idx / HD, u = idx - b * HD;
    const float* g = g_gates + b * G4H;
    float gi = g[u], gf = g[u + HD], gg = g[u + 2 * HD], go = g[u + 3 * HD];
    float si = 1.f / (1.f + expf(-gi));
    float sf = 1.f / (1.f + expf(-gf));
    float so = 1.f / (1.f + expf(-go));
    float c = sf * g_c[idx] + si * tanhf(gg);
    float h = so * tanhf(c);
    g_c[idx] = c;
    g_h[idx] = h;
}

// ---------------- G3: scores tf32x3-MMA GEMM + mask + gumbel + partial argmax ----------------
// C[v][b], block = 128 v x 64 b, 8 warps as 2(v) x 4(b), warp tile 64x16.
__global__ __launch_bounds__(256) void scores_mma_kernel(
    const float* __restrict__ out_W, const float* __restrict__ out_b,
    const unsigned* __restrict__ order_masks, float* __restrict__ scores_out, int t) {
    __shared__ __align__(16) unsigned AsH[128][20];
    __shared__ __align__(16) unsigned AsL[128][20];
    __shared__ __align__(16) unsigned BsH[64][20];
    __shared__ __align__(16) unsigned BsL[64][20];
    __shared__ unsigned long long sbest[64];
    __shared__ float sOutB[128];
    int tid = threadIdx.x;
    int v0 = blockIdx.x * 128, b0 = blockIdx.y * 64;
    int lane = tid & 31, warp = tid >> 5;
    int wv = warp & 1, wb = warp >> 1;
    int g = lane >> 2, tig = lane & 3;

    if (tid < 64) sbest[tid] = 0ULL;
    if (tid < 128) {
        int v = v0 + tid;
        sOutB[tid] = (v < VV) ? out_b[v] : 0.f;
    }

    float acc[4][2][4];
#pragma unroll
    for (int mt = 0; mt < 4; ++mt)
#pragma unroll
        for (int nt = 0; nt < 2; ++nt)
#pragma unroll
            for (int q = 0; q < 4; ++q) acc[mt][nt][q] = 0.f;

    int arow = tid >> 1, akp = (tid & 1) * 8;
    int brow = tid >> 2, bkp = (tid & 3) * 4;

    for (int k0 = 0; k0 < 208; k0 += 16) {
        // A = out_W rows (v)
        int v = v0 + arow;
#pragma unroll
        for (int half = 0; half < 2; ++half) {
            int k = k0 + akp + half * 4;
            float4 a = make_float4(0.f, 0.f, 0.f, 0.f);
            if (v < VV && k < HD) a = *(const float4*)(out_W + (size_t)v * HD + k);
            uint4 hi, lo; split4(a, hi, lo);
            *(uint4*)&AsH[arow][akp + half * 4] = hi;
            *(uint4*)&AsL[arow][akp + half * 4] = lo;
        }
        // B = h rows (b)
        {
            int bb = b0 + brow;
            int k = k0 + bkp;
            float4 x = make_float4(0.f, 0.f, 0.f, 0.f);
            if (k < HD) x = *(const float4*)(g_h + bb * HD + k);
            uint4 hi, lo; split4(x, hi, lo);
            *(uint4*)&BsH[brow][bkp] = hi;
            *(uint4*)&BsL[brow][bkp] = lo;
        }
        __syncthreads();
#pragma unroll
        for (int kk = 0; kk < 16; kk += 8) {
            unsigned afh[4][4], afl[4][4], bfh[2][2], bfl[2][2];
#pragma unroll
            for (int mt = 0; mt < 4; ++mt) {
                int r = wv * 64 + mt * 16 + g;
                afh[mt][0] = AsH[r][kk + tig];
                afh[mt][1] = AsH[r + 8][kk + tig];
                afh[mt][2] = AsH[r][kk + tig + 4];
                afh[mt][3] = AsH[r + 8][kk + tig + 4];
                afl[mt][0] = AsL[r][kk + tig];
                afl[mt][1] = AsL[r + 8][kk + tig];
                afl[mt][2] = AsL[r][kk + tig + 4];
                afl[mt][3] = AsL[r + 8][kk + tig + 4];
            }
#pragma unroll
            for (int nt = 0; nt < 2; ++nt) {
                int c = wb * 16 + nt * 8 + g;
                bfh[nt][0] = BsH[c][kk + tig];
                bfh[nt][1] = BsH[c][kk + tig + 4];
                bfl[nt][0] = BsL[c][kk + tig];
                bfl[nt][1] = BsL[c][kk + tig + 4];
            }
#pragma unroll
            for (int mt = 0; mt < 4; ++mt)
#pragma unroll
                for (int nt = 0; nt < 2; ++nt) {
                    mma_tf32(acc[mt][nt], afh[mt], bfl[nt]);
                    mma_tf32(acc[mt][nt], afl[mt], bfh[nt]);
                    mma_tf32(acc[mt][nt], afh[mt], bfh[nt]);
                }
        }
        __syncthreads();
    }

    // ---- epilogue: bias + mask + scores write + gumbel argmax ----
    unsigned k1t = g_keys[2 * t], k2t = g_keys[2 * t + 1];
    bool wr = (scores_out != nullptr);
#pragma unroll
    for (int nt = 0; nt < 2; ++nt)
#pragma unroll
        for (int cc = 0; cc < 2; ++cc) {
            int b = b0 + wb * 16 + nt * 8 + 2 * tig + cc;
            int inv = g_invalid[b];
            unsigned long long best = 0ULL;
#pragma unroll
            for (int mt = 0; mt < 4; ++mt)
#pragma unroll
                for (int rr = 0; rr < 2; ++rr) {
                    int v = v0 + wv * 64 + mt * 16 + g + rr * 8;
                    if (v >= VV) continue;
                    float s = acc[mt][nt][rr * 2 + cc] + sOutB[v - v0];
                    size_t mi = ((size_t)b * SS + t) * (size_t)VV + v;
                    bool m = inv || (order_masks[mi] != 0u);
                    float sm = fminf(s, m ? 9.0e8f : -1.0e8f);
                    if (wr) scores_out[mi] = sm;
                    if (m) {
                        unsigned n = (unsigned)(b * VV + v);
                        uint2 r = tf2x32(k1t, k2t, 0u, n);
                        unsigned bits = r.x ^ r.y;
                        float uf = __uint_as_float((bits >> 9) | 0x3F800000u) - 1.0f;
                        uf = fmaxf(uf + 1.17549435e-38f, 1.17549435e-38f);
                        float gum = -alogf(-alogf(uf));
                        float cand = sm + gum;
                        unsigned ub = __float_as_uint(cand);
                        ub = (ub & 0x80000000u) ? ~ub : (ub | 0x80000000u);
                        unsigned long long packed =
                            ((unsigned long long)ub << 32) | (unsigned)(~(unsigned)v);
                        if (packed > best) best = packed;
                    }
                }
            if (best) atomicMax(&sbest[b - b0], best);
        }
    __syncthreads();
    if (tid < 64 && sbest[tid]) atomicMax(&g_amax[b0 + tid], sbest[tid]);
}

// ---------------- G4: finalize sample -> idx output + order embedding, reset slot ----------------
__global__ void sample_finish_kernel(const float* __restrict__ order_embedding,
                                     float* __restrict__ idx_out, int t) {
    int b = blockIdx.x;
    __shared__ int sidx;
    if (threadIdx.x == 0) {
        unsigned long long p = g_amax[b];
        int idx = (p == 0ULL) ? 0 : (int)(~(unsigned)(p & 0xFFFFFFFFu));
        if (idx < 0) idx = 0;
        if (idx >= VV) idx = VV - 1;
        sidx = idx;
        g_amax[b] = 0ULL;
        if (idx_out) idx_out[b * SS + t] = (float)idx;
    }
    __syncthreads();
    int idx = sidx;
    if (threadIdx.x < OED)
        g_oe[b * OED + threadIdx.x] = order_embedding[(size_t)idx * OED + threadIdx.x];
}

// ---------------- launch ----------------
extern "C" void kernel_launch(void* const* d_in, const int* in_sizes, int n_in,
                              void* d_out, int out_size) {
    const float*    enc        = (const float*)d_in[0];
    const int*      loc_idxs   = (const int*)d_in[2];
    const unsigned* ord_masks  = (const unsigned*)d_in[3];
    const float*    power_1h   = (const float*)d_in[4];
    const float*    order_emb  = (const float*)d_in[5];
    const float*    power_W    = (const float*)d_in[6];
    const float*    power_b    = (const float*)d_in[7];
    const float*    W_ih       = (const float*)d_in[8];
    const float*    W_hh       = (const float*)d_in[9];
    const float*    b_ih       = (const float*)d_in[10];
    const float*    b_hh       = (const float*)d_in[11];
    const float*    out_W      = (const float*)d_in[12];
    const float*    out_b      = (const float*)d_in[13];
    const float*    master     = (const float*)d_in[14];

    float* out = (float*)d_out;
    float* idx_out = nullptr;
    float* scores_out = nullptr;
    const long long NSC = (long long)BB * SS * VV;
    if ((long long)out_size == NSC + (long long)BB * SS) { idx_out = out; scores_out = out + BB * SS; }
    else if ((long long)out_size == NSC)                 { scores_out = out; }
    else if (out_size == BB * SS)                        { idx_out = out; }
    else { scores_out = out; }

    precompute_kernel<<<BB, 256>>>(enc, loc_idxs, power_1h, power_W, power_b, master);

    dim3 g1grid((G4H + 127) / 128, BB / 64);         // 7 x 8
    dim3 g3grid((VV + 127) / 128, BB / 64);          // 102 x 8
    for (int t = 0; t < SS; ++t) {
        gates_mma_kernel<<<g1grid, 256>>>(W_ih, W_hh, b_ih, b_hh, t);
        lstm_update_kernel<<<(BB * HD + 255) / 256, 256>>>();
        scores_mma_kernel<<<g3grid, 256>>>(out_W, out_b, ord_masks, scores_out, t);
        sample_finish_kernel<<<BB, 128>>>(order_emb, idx_out, t);
    }
}

// round 7
// speedup vs baseline: 1.1737x; 1.0318x over previous
#include <cuda_runtime.h>

#define BB   512
#define SS   17
#define LL   81
#define VV   13030
#define ENCD 240
#define OED  80
#define PED  60
#define IND  380     // ENC + OE + PE
#define HD   200
#define G4H  800     // 4*H
#define KIN  580     // IND + HD

// ---------------- scratch (static device globals; no allocation) ----------------
__device__ __align__(16) float g_loc_enc[SS * BB * ENCD];     // [t][b][d]
__device__ __align__(16) float g_power_emb[BB * PED];
__device__ int   g_invalid[BB];
__device__ __align__(16) float g_h[BB * HD];
__device__ __align__(16) float g_c[BB * HD];
__device__ __align__(16) float g_oe[BB * OED];
__device__ __align__(16) float g_gates[BB * G4H];
__device__ unsigned g_keys[2 * SS];             // (k1,k2) per step
__device__ __align__(16) float g_scores[BB * VV];  // scratch when no scores output

// ---------------- threefry2x32 (matches jax/_src/prng.py reference) ----------------
__device__ __forceinline__ uint2 tf2x32(unsigned k0, unsigned k1,
                                        unsigned x0, unsigned x1) {
    unsigned ks2 = k0 ^ k1 ^ 0x1BD11BDAu;
    x0 += k0; x1 += k1;
#define TFR(r) { x0 += x1; x1 = __funnelshift_l(x1, x1, (r)); x1 ^= x0; }
    TFR(13) TFR(15) TFR(26) TFR(6)
    x0 += k1; x1 += ks2 + 1u;
    TFR(17) TFR(29) TFR(16) TFR(24)
    x0 += ks2; x1 += k0 + 2u;
    TFR(13) TFR(15) TFR(26) TFR(6)
    x0 += k0; x1 += k1 + 3u;
    TFR(17) TFR(29) TFR(16) TFR(24)
    x0 += k1; x1 += ks2 + 4u;
    TFR(13) TFR(15) TFR(26) TFR(6)
    x0 += ks2; x1 += k0 + 5u;
#undef TFR
    return make_uint2(x0, x1);
}

// ---------------- accurate fp32 natural log (fdlibm e_logf; fast-math-proof) ----------------
__device__ __forceinline__ float alogf(float x) {
    int ib = __float_as_int(x);
    int k  = ((ib >> 23) & 0xFF) - 126;
    float m = __int_as_float((ib & 0x007FFFFF) | 0x3F000000);  // [0.5,1)
    if (m < 0.70710678f) { m = m + m; k -= 1; }
    float f = m - 1.0f;
    float s = f / (2.0f + f);
    float z = s * s;
    float w = z * z;
    float t1 = w * (0.40000972152f + w * 0.24279078841f);
    float t2 = z * (0.66666662693f + w * 0.28498786688f);
    float R  = t2 + t1;
    float hfsq = 0.5f * f * f;
    float dk = (float)k;
    return dk * 0.69313812256f - ((hfsq - (s * (hfsq + R) + dk * 9.0580006145e-06f)) - f);
}

// ---------------- tf32 helpers ----------------
__device__ __forceinline__ unsigned f2tf32(float x) {
    unsigned r;
    asm("cvt.rna.tf32.f32 %0, %1;" : "=r"(r) : "f"(x));
    return r;
}
__device__ __forceinline__ void mma_tf32(float* c, const unsigned* a, const unsigned* b) {
    asm volatile(
        "mma.sync.aligned.m16n8k8.row.col.f32.tf32.tf32.f32 "
        "{%0,%1,%2,%3}, {%4,%5,%6,%7}, {%8,%9}, {%0,%1,%2,%3};\n"
        : "+f"(c[0]), "+f"(c[1]), "+f"(c[2]), "+f"(c[3])
        : "r"(a[0]), "r"(a[1]), "r"(a[2]), "r"(a[3]), "r"(b[0]), "r"(b[1]));
}
__device__ __forceinline__ void split1(float x, unsigned& hi, unsigned& lo) {
    hi = f2tf32(x);
    lo = f2tf32(x - __uint_as_float(hi));
}
__device__ __forceinline__ void split4(float4 v, uint4& hi, uint4& lo) {
    split1(v.x, hi.x, lo.x);
    split1(v.y, hi.y, lo.y);
    split1(v.z, hi.z, lo.z);
    split1(v.w, hi.w, lo.w);
}

// ---------------- kernel A: precompute (unchanged, known-correct) ----------------
__global__ __launch_bounds__(256) void precompute_kernel(
    const float* __restrict__ enc, const int* __restrict__ loc_idxs,
    const float* __restrict__ power_1h, const float* __restrict__ power_W,
    const float* __restrict__ power_b, const float* __restrict__ master) {
    __shared__ float sM[LL * LL];
    __shared__ float sAl[SS][LL];
    __shared__ float sDen[SS];
    __shared__ int   sLoc[LL];
    int b = blockIdx.x;
    int tid = threadIdx.x;

    for (int i = tid; i < LL * LL; i += 256) sM[i] = master[i];
    if (tid < LL) sLoc[tid] = loc_idxs[b * LL + tid];
    for (int i = tid; i < HD; i += 256) { g_h[b * HD + i] = 0.f; g_c[b * HD + i] = 0.f; }
    for (int i = tid; i < OED; i += 256) g_oe[b * OED + i] = 0.f;
    if (tid < PED) {
        float acc = power_b[tid];
        for (int j = 0; j < 7; ++j) acc += power_1h[b * 7 + j] * power_W[tid * 7 + j];
        g_power_emb[b * PED + tid] = acc;
    }
    if (b == 0 && tid < SS) {
        uint2 r = tf2x32(0u, 42u, 0u, (unsigned)tid);
        g_keys[2 * tid]     = r.x;
        g_keys[2 * tid + 1] = r.y;
    }
    __syncthreads();

    if (tid == 0) {
        int any = 0;
        for (int l = 0; l < LL; ++l) any |= (sLoc[l] != -1);
        g_invalid[b] = !any;
    }
    for (int e = tid; e < SS * LL; e += 256) {
        int t = e / LL, j = e % LL;
        float a = 0.f;
        for (int l = 0; l < LL; ++l) {
            int li = sLoc[l];
            if (li == t || li == -2) a += sM[l * LL + j];
        }
        sAl[t][j] = a;
    }
    __syncthreads();
    if (tid < SS) {
        float d = 0.f;
        for (int j = 0; j < LL; ++j) d += sAl[tid][j];
        sDen[tid] = d;
    }
    __syncthreads();
    for (int e = tid; e < SS * LL; e += 256) {
        int t = e / LL, j = e % LL;
        float d = sDen[t];
        sAl[t][j] = (d != 0.f) ? sAl[t][j] / d : 0.f;
    }
    __syncthreads();
    if (tid < ENCD) {
        float acc[SS];
#pragma unroll
        for (int t = 0; t < SS; ++t) acc[t] = 0.f;
        for (int l = 0; l < LL; ++l) {
            float v = enc[((size_t)b * LL + l) * ENCD + tid];
#pragma unroll
            for (int t = 0; t < SS; ++t) acc[t] += sAl[t][l] * v;
        }
#pragma unroll
        for (int t = 0; t < SS; ++t)
            g_loc_enc[((size_t)t * BB + b) * ENCD + tid] = acc[t];
    }
}

// ---------------- G1: gates tf32x3-MMA GEMM (unchanged, known-correct) ----------------
__global__ __launch_bounds__(256) void gates_mma_kernel(
    const float* __restrict__ W_ih, const float* __restrict__ W_hh,
    const float* __restrict__ b_ih, const float* __restrict__ b_hh, int t) {
    __shared__ __align__(16) unsigned AsH[128][20];
    __shared__ __align__(16) unsigned AsL[128][20];
    __shared__ __align__(16) unsigned BsH[64][20];
    __shared__ __align__(16) unsigned BsL[64][20];
    __shared__ float sBias[128];
    int tid = threadIdx.x;
    int u0 = blockIdx.x * 128, b0 = blockIdx.y * 64;
    int lane = tid & 31, warp = tid >> 5;
    int wv = warp & 1, wb = warp >> 1;
    int g = lane >> 2, tig = lane & 3;
    const float* locenc = g_loc_enc + (size_t)t * BB * ENCD;

    if (tid < 128) {
        int u = u0 + tid;
        sBias[tid] = (u < G4H) ? (b_ih[u] + b_hh[u]) : 0.f;
    }

    float acc[4][2][4];
#pragma unroll
    for (int mt = 0; mt < 4; ++mt)
#pragma unroll
        for (int nt = 0; nt < 2; ++nt)
#pragma unroll
            for (int q = 0; q < 4; ++q) acc[mt][nt][q] = 0.f;

    int arow = tid >> 1, akp = (tid & 1) * 8;
    int brow = tid >> 2, bkp = (tid & 3) * 4;

    for (int k0 = 0; k0 < 592; k0 += 16) {
        int u = u0 + arow;
#pragma unroll
        for (int half = 0; half < 2; ++half) {
            int k = k0 + akp + half * 4;
            float4 a = make_float4(0.f, 0.f, 0.f, 0.f);
            if (u < G4H) {
                if (k < HD)       a = *(const float4*)(W_hh + (size_t)u * HD + k);
                else if (k < KIN) a = *(const float4*)(W_ih + (size_t)u * IND + (k - HD));
            }
            uint4 hi, lo; split4(a, hi, lo);
            *(uint4*)&AsH[arow][akp + half * 4] = hi;
            *(uint4*)&AsL[arow][akp + half * 4] = lo;
        }
        {
            int bb = b0 + brow;
            int k = k0 + bkp;
            float4 x = make_float4(0.f, 0.f, 0.f, 0.f);
            if (k < HD)                   x = *(const float4*)(g_h + bb * HD + k);
            else if (k < HD + ENCD)       x = *(const float4*)(locenc + bb * ENCD + (k - HD));
            else if (k < HD + ENCD + OED) x = *(const float4*)(g_oe + bb * OED + (k - HD - ENCD));
            else if (k < KIN)             x = *(const float4*)(g_power_emb + bb * PED + (k - HD - ENCD - OED));
            uint4 hi, lo; split4(x, hi, lo);
            *(uint4*)&BsH[brow][bkp] = hi;
            *(uint4*)&BsL[brow][bkp] = lo;
        }
        __syncthreads();
#pragma unroll
        for (int kk = 0; kk < 16; kk += 8) {
            unsigned afh[4][4], afl[4][4], bfh[2][2], bfl[2][2];
#pragma unroll
            for (int mt = 0; mt < 4; ++mt) {
                int r = wv * 64 + mt * 16 + g;
                afh[mt][0] = AsH[r][kk + tig];
                afh[mt][1] = AsH[r + 8][kk + tig];
                afh[mt][2] = AsH[r][kk + tig + 4];
                afh[mt][3] = AsH[r + 8][kk + tig + 4];
                afl[mt][0] = AsL[r][kk + tig];
                afl[mt][1] = AsL[r + 8][kk + tig];
                afl[mt][2] = AsL[r][kk + tig + 4];
                afl[mt][3] = AsL[r + 8][kk + tig + 4];
            }
#pragma unroll
            for (int nt = 0; nt < 2; ++nt) {
                int c = wb * 16 + nt * 8 + g;
                bfh[nt][0] = BsH[c][kk + tig];
                bfh[nt][1] = BsH[c][kk + tig + 4];
                bfl[nt][0] = BsL[c][kk + tig];
                bfl[nt][1] = BsL[c][kk + tig + 4];
            }
#pragma unroll
            for (int mt = 0; mt < 4; ++mt)
#pragma unroll
                for (int nt = 0; nt < 2; ++nt) {
                    mma_tf32(acc[mt][nt], afh[mt], bfl[nt]);
                    mma_tf32(acc[mt][nt], afl[mt], bfh[nt]);
                    mma_tf32(acc[mt][nt], afh[mt], bfh[nt]);
                }
        }
        __syncthreads();
    }
#pragma unroll
    for (int nt = 0; nt < 2; ++nt)
#pragma unroll
        for (int cc = 0; cc < 2; ++cc) {
            int b = b0 + wb * 16 + nt * 8 + 2 * tig + cc;
#pragma unroll
            for (int mt = 0; mt < 4; ++mt)
#pragma unroll
                for (int rr = 0; rr < 2; ++rr) {
                    int u = u0 + wv * 64 + mt * 16 + g + rr * 8;
                    if (u < G4H)
                        g_gates[b * G4H + u] = acc[mt][nt][rr * 2 + cc] + sBias[u - u0];
                }
        }
}

// ---------------- G2: LSTM pointwise update ----------------
__global__ void lstm_update_kernel() {
    int idx = blockIdx.x * blockDim.x + threadIdx.x;
    if (idx >= BB * HD) return;
    int b = idx / HD, u = idx - b * HD;
    const float* g = g_gates + b * G4H;
    float gi = g[u], gf = g[u + HD], gg = g[u + 2 * HD], go = g[u + 3 * HD];
    float si = 1.f / (1.f + expf(-gi));
    float sf = 1.f / (1.f + expf(-gf));
    float so = 1.f / (1.f + expf(-go));
    float c = sf * g_c[idx] + si * tanhf(gg);
    float h = so * tanhf(c);
    g_c[idx] = c;
    g_h[idx] = h;
}

// ---------------- G3: scores tf32x3-MMA GEMM, coalesced mask+bias epilogue ----------------
// C[v][b] tiles, 128v x 64b; epilogue transposes through smem, writes [b][v] float2-coalesced.
struct SUnion {
    union {
        struct {
            unsigned AsH[128][20];
            unsigned AsL[128][20];
            unsigned BsH[64][20];
            unsigned BsL[64][20];
        } p;
        float C[64][132];
    };
};

__global__ __launch_bounds__(256) void scores_mma_kernel(
    const float* __restrict__ out_W, const float* __restrict__ out_b,
    const unsigned* __restrict__ order_masks,
    float* __restrict__ sc_base, long long pitch, long long off, int t) {
    __shared__ SUnion u;
    __shared__ float sOutB[128];
    int tid = threadIdx.x;
    int v0 = blockIdx.x * 128, b0 = blockIdx.y * 64;
    int lane = tid & 31, warp = tid >> 5;
    int wv = warp & 1, wb = warp >> 1;
    int g = lane >> 2, tig = lane & 3;

    if (tid < 128) {
        int v = v0 + tid;
        sOutB[tid] = (v < VV) ? out_b[v] : 0.f;
    }

    float acc[4][2][4];
#pragma unroll
    for (int mt = 0; mt < 4; ++mt)
#pragma unroll
        for (int nt = 0; nt < 2; ++nt)
#pragma unroll
            for (int q = 0; q < 4; ++q) acc[mt][nt][q] = 0.f;

    int arow = tid >> 1, akp = (tid & 1) * 8;
    int brow = tid >> 2, bkp = (tid & 3) * 4;

    for (int k0 = 0; k0 < 208; k0 += 16) {
        int v = v0 + arow;
#pragma unroll
        for (int half = 0; half < 2; ++half) {
            int k = k0 + akp + half * 4;
            float4 a = make_float4(0.f, 0.f, 0.f, 0.f);
            if (v < VV && k < HD) a = *(const float4*)(out_W + (size_t)v * HD + k);
            uint4 hi, lo; split4(a, hi, lo);
            *(uint4*)&u.p.AsH[arow][akp + half * 4] = hi;
            *(uint4*)&u.p.AsL[arow][akp + half * 4] = lo;
        }
        {
            int bb = b0 + brow;
            int k = k0 + bkp;
            float4 x = make_float4(0.f, 0.f, 0.f, 0.f);
            if (k < HD) x = *(const float4*)(g_h + bb * HD + k);
            uint4 hi, lo; split4(x, hi, lo);
            *(uint4*)&u.p.BsH[brow][bkp] = hi;
            *(uint4*)&u.p.BsL[brow][bkp] = lo;
        }
        __syncthreads();
#pragma unroll
        for (int kk = 0; kk < 16; kk += 8) {
            unsigned afh[4][4], afl[4][4], bfh[2][2], bfl[2][2];
#pragma unroll
            for (int mt = 0; mt < 4; ++mt) {
                int r = wv * 64 + mt * 16 + g;
                afh[mt][0] = u.p.AsH[r][kk + tig];
                afh[mt][1] = u.p.AsH[r + 8][kk + tig];
                afh[mt][2] = u.p.AsH[r][kk + tig + 4];
                afh[mt][3] = u.p.AsH[r + 8][kk + tig + 4];
                afl[mt][0] = u.p.AsL[r][kk + tig];
                afl[mt][1] = u.p.AsL[r + 8][kk + tig];
                afl[mt][2] = u.p.AsL[r][kk + tig + 4];
                afl[mt][3] = u.p.AsL[r + 8][kk + tig + 4];
            }
#pragma unroll
            for (int nt = 0; nt < 2; ++nt) {
                int c = wb * 16 + nt * 8 + g;
                bfh[nt][0] = u.p.BsH[c][kk + tig];
                bfh[nt][1] = u.p.BsH[c][kk + tig + 4];
                bfl[nt][0] = u.p.BsL[c][kk + tig];
                bfl[nt][1] = u.p.BsL[c][kk + tig + 4];
            }
#pragma unroll
            for (int mt = 0; mt < 4; ++mt)
#pragma unroll
                for (int nt = 0; nt < 2; ++nt) {
                    mma_tf32(acc[mt][nt], afh[mt], bfl[nt]);
                    mma_tf32(acc[mt][nt], afl[mt], bfh[nt]);
                    mma_tf32(acc[mt][nt], afh[mt], bfh[nt]);
                }
        }
        __syncthreads();
    }

    // ---- transpose accumulators through smem (conflict-free banks) ----
#pragma unroll
    for (int nt = 0; nt < 2; ++nt)
#pragma unroll
        for (int cc = 0; cc < 2; ++cc) {
            int bl = wb * 16 + nt * 8 + 2 * tig + cc;
#pragma unroll
            for (int mt = 0; mt < 4; ++mt)
#pragma unroll
                for (int rr = 0; rr < 2; ++rr) {
                    int vl = wv * 64 + mt * 16 + g + rr * 8;
                    u.C[bl][vl] = acc[mt][nt][rr * 2 + cc];
                }
        }
    __syncthreads();

    // ---- coalesced store: float2 per lane (8B-aligned everywhere; VV even) ----
    for (int e = tid; e < 64 * 64; e += 256) {
        int bl = e >> 6, v2 = e & 63;
        int b = b0 + bl;
        int v = v0 + v2 * 2;
        if (v >= VV) continue;
        float2 c = *(float2*)&u.C[bl][v2 * 2];
        c.x += sOutB[v2 * 2];
        c.y += sOutB[v2 * 2 + 1];
        int inv = g_invalid[b];
        uint2 m2 = *(const uint2*)(order_masks + ((size_t)b * SS + t) * VV + v);
        bool ma = inv || (m2.x != 0u);
        bool mb = inv || (m2.y != 0u);
        float2 r;
        r.x = fminf(c.x, ma ? 9.0e8f : -1.0e8f);
        r.y = fminf(c.y, mb ? 9.0e8f : -1.0e8f);
        *(float2*)(sc_base + (long long)b * pitch + off + v) = r;
    }
}

// ---------------- G4: sample kernel — ballot-compacted gumbel argmax + finish ----------------
// candidate <=> score != -1e8f exactly (masked-out entries are exactly -1e8f).
__device__ __forceinline__ float gproc(float sm, int vv, int b,
                                       unsigned k1t, unsigned k2t,
                                       float rb, unsigned long long& best) {
    uint2 r = tf2x32(k1t, k2t, 0u, (unsigned)(b * VV + vv));
    unsigned bits = r.x ^ r.y;
    float uf = __uint_as_float((bits >> 9) | 0x3F800000u) - 1.0f;
    uf = fmaxf(uf + 1.17549435e-38f, 1.17549435e-38f);
    // cheap certified gumbel upper bound:
    // lnap(x) = bits(x)*ln2/2^23 - 127*ln2 satisfies lnap <= ln x <= lnap + 0.05966 (+rounding)
    float lnu_lo = fmaf((float)__float_as_int(uf), 8.2629582e-8f, -88.029694f);
    float e_min = -lnu_lo - 0.0605f;          // guaranteed <= -ln(uf)
    float gub = 3.0e38f;
    if (e_min > 1.17549435e-38f) {
        float lne_lo = fmaf((float)__float_as_int(e_min), 8.2629582e-8f, -88.029694f);
        gub = -lne_lo + 1.0e-3f;              // guaranteed >= gumbel (safety margin)
    }
    if (sm + gub < rb) return -3.0e38f;       // provably cannot win
    float gum = -alogf(-alogf(uf));           // exact path: identical to prior rounds
    float cv = sm + gum;
    unsigned ub = __float_as_uint(cv);
    ub = (ub & 0x80000000u) ? ~ub : (ub | 0x80000000u);
    unsigned long long packed = ((unsigned long long)ub << 32) | (unsigned)(~(unsigned)vv);
    if (packed > best) best = packed;
    return cv;
}

__global__ __launch_bounds__(256) void sample_kernel(
    const float* __restrict__ sc_base, long long pitch, long long off,
    const float* __restrict__ order_embedding, float* __restrict__ idx_out, int t) {
    int b = blockIdx.x;
    const float* row = sc_base + (long long)b * pitch + off;
    int tid = threadIdx.x, warp = tid >> 5, lane = tid & 31;
    __shared__ unsigned short qv[8][64];
    __shared__ float qs[8][64];
    __shared__ unsigned long long wbest[8];
    __shared__ int sidx;
    unsigned k1t = g_keys[2 * t], k2t = g_keys[2 * t + 1];
    const int SEG = 1632;                       // 8*1632 >= VV, multiple of 32
    int s0 = warp * SEG;
    int s1 = min(s0 + SEG, VV);
    unsigned long long best = 0ULL;
    float rb = -3.0e38f;
    int qh = 0, qt = 0;

    for (int v0 = s0; v0 < s1; v0 += 32) {
        int v = v0 + lane;
        float sv = (v < s1) ? row[v] : -1.0e8f;
        bool cand = (v < s1) && (sv != -1.0e8f);
        unsigned mk = __ballot_sync(0xffffffffu, cand);
        int rank = __popc(mk & ((1u << lane) - 1u));
        if (cand) {
            int p = (qt + rank) & 63;
            qv[warp][p] = (unsigned short)v;
            qs[warp][p] = sv;
        }
        qt += __popc(mk);
        while (qt - qh >= 32) {
            __syncwarp();
            int p = (qh + lane) & 63;
            int vv = qv[warp][p];
            float sm = qs[warp][p];
            __syncwarp();
            qh += 32;
            float cv = gproc(sm, vv, b, k1t, k2t, rb, best);
            // warp-max of exact values -> running best for the filter
#pragma unroll
            for (int o = 16; o; o >>= 1)
                cv = fmaxf(cv, __shfl_xor_sync(0xffffffffu, cv, o));
            rb = fmaxf(rb, cv);
        }
    }
    // drain remainder
    {
        int rem = qt - qh;
        __syncwarp();
        if (lane < rem) {
            int p = (qh + lane) & 63;
            int vv = qv[warp][p];
            float sm = qs[warp][p];
            (void)gproc(sm, vv, b, k1t, k2t, rb, best);
        }
    }
    // warp reduce packed best
#pragma unroll
    for (int o = 16; o; o >>= 1) {
        unsigned long long ob = __shfl_xor_sync(0xffffffffu, best, o);
        if (ob > best) best = ob;
    }
    if (lane == 0) wbest[warp] = best;
    __syncthreads();
    if (tid == 0) {
        unsigned long long bb = 0ULL;
#pragma unroll
        for (int w = 0; w < 8; ++w) bb = (wbest[w] > bb) ? wbest[w] : bb;
        int idx = (bb == 0ULL) ? 0 : (int)(~(unsigned)(bb & 0xFFFFFFFFu));
        if (idx < 0) idx = 0;
        if (idx >= VV) idx = VV - 1;
        sidx = idx;
        if (idx_out) idx_out[b * SS + t] = (float)idx;
    }
    __syncthreads();
    if (tid < OED)
        g_oe[b * OED + tid] = order_embedding[(size_t)sidx * OED + tid];
}

// ---------------- launch ----------------
extern "C" void kernel_launch(void* const* d_in, const int* in_sizes, int n_in,
                              void* d_out, int out_size) {
    const float*    enc        = (const float*)d_in[0];
    const int*      loc_idxs   = (const int*)d_in[2];
    const unsigned* ord_masks  = (const unsigned*)d_in[3];
    const float*    power_1h   = (const float*)d_in[4];
    const float*    order_emb  = (const float*)d_in[5];
    const float*    power_W    = (const float*)d_in[6];
    const float*    power_b    = (const float*)d_in[7];
    const float*    W_ih       = (const float*)d_in[8];
    const float*    W_hh       = (const float*)d_in[9];
    const float*    b_ih       = (const float*)d_in[10];
    const float*    b_hh       = (const float*)d_in[11];
    const float*    out_W      = (const float*)d_in[12];
    const float*    out_b      = (const float*)d_in[13];
    const float*    master     = (const float*)d_in[14];

    float* out = (float*)d_out;
    float* idx_out = nullptr;
    float* scores_out = nullptr;
    const long long NSC = (long long)BB * SS * VV;
    if ((long long)out_size == NSC + (long long)BB * SS) { idx_out = out; scores_out = out + BB * SS; }
    else if ((long long)out_size == NSC)                 { scores_out = out; }
    else if (out_size == BB * SS)                        { idx_out = out; }
    else { scores_out = out; }

    // scores destination: real output if present, else device scratch
    float* g_scores_ptr = nullptr;
    cudaGetSymbolAddress((void**)&g_scores_ptr, g_scores);
    float*    sc_base = scores_out ? scores_out : g_scores_ptr;
    long long pitch   = scores_out ? (long long)SS * VV : (long long)VV;

    precompute_kernel<<<BB, 256>>>(enc, loc_idxs, power_1h, power_W, power_b, master);

    dim3 g1grid((G4H + 127) / 128, BB / 64);         // 7 x 8
    dim3 g3grid((VV + 127) / 128, BB / 64);          // 102 x 8
    for (int t = 0; t < SS; ++t) {
        long long off = scores_out ? (long long)t * VV : 0;
        gates_mma_kernel<<<g1grid, 256>>>(W_ih, W_hh, b_ih, b_hh, t);
        lstm_update_kernel<<<(BB * HD + 255) / 256, 256>>>();
        scores_mma_kernel<<<g3grid, 256>>>(out_W, out_b, ord_masks, sc_base, pitch, off, t);
        sample_kernel<<<BB, 256>>>(sc_base, pitch, off, order_emb, idx_out, t);
    }
}